// round 6
// baseline (speedup 1.0000x reference)
#include <cuda_runtime.h>
#include <cuda_bf16.h>

// ROCModel: per-row weighted histogram (searchsorted into linspace(0,1,100)),
// suffix-sum ROC curves, derivative curves, trapz integrals.
//
// R6 (= R5 resubmit; R5 hit a broker-level container failure, uncorrelated
// with kernel content — R4 with near-identical structure ran fine).
// Theory: still DRAM-latency-bound at 12 warps/SM. Deepen rolling prefetch
// CHUNK 8->12 (~12-24 LDG.128 in flight per thread across the burst),
// __ldcs streaming loads (x is read-once; don't thrash L2).
// Hist layout / bin math unchanged (exact, conflict-free).

#define MBINS 100
#define TPB   128
#define CHUNK 12         // float4 per thread per chunk

__global__ __launch_bounds__(TPB)
void roc_kernel(const float* __restrict__ x,
                const float* __restrict__ y,
                float* __restrict__ out,
                int B, int N)
{
    extern __shared__ float smem[];
    float* hist = smem;                       // [MBINS][TPB] per-thread private
    float* trep = smem + MBINS * TPB;         // [MBINS][32]  t replicated per lane
    float* bsum = trep + MBINS * 32;          // [MBINS]
    float* ssum = bsum + MBINS;               // [MBINS]
    float* tz   = ssum + MBINS;               // [2]

    const int tid  = threadIdx.x;
    const int lane = tid & 31;
    const int row  = blockIdx.x;

    // ---- init ----
    for (int i = tid; i < MBINS * TPB; i += TPB) hist[i] = 0.0f;
    for (int e = tid; e < MBINS * 32; e += TPB) {
        int j = e >> 5;
        // JAX linspace(0,1,100): t[i] = fl(i/99) (RN), t[99] = 1.0 exactly
        trep[e] = (j == MBINS - 1) ? 1.0f : __fdiv_rn((float)j, (float)(MBINS - 1));
    }
    if (tid < 2) tz[tid] = 0.0f;
    __syncthreads();

    const float* xrow = x + (size_t)row * (size_t)N;
    const float4* xr4 = (const float4*)xrow;
    const int n4 = N >> 2;

    const float* tlane = trep + lane;         // this lane's t replica base
    float* hbase = hist + tid;                // this thread's hist column

    // Exact bin: c = #{i in 0..99 : t[i] < x}. g = floor(fl(99*x)) is within
    // 1 ulp of the true cell, so checking t[g], t[g+1] suffices. g<=98.
    auto proc = [&](float xv) {
        int g = __float2int_rd(__fmul_rn(xv, (float)(MBINS - 1)));
        g = min(g, MBINS - 2);
        const float t0 = tlane[g << 5];
        const float t1 = tlane[(g << 5) + 32];
        const int c = g + (t0 < xv) + (t1 < xv);
        hbase[c * TPB] += xv;
    };

    const int STEP  = CHUNK * TPB;            // float4s consumed per chunk
    const int nfull = n4 / STEP;

    if (nfull > 0) {
        float4 buf[CHUNK];
        int base = tid;
        // prime
        #pragma unroll
        for (int k = 0; k < CHUNK; ++k) buf[k] = __ldcs(&xr4[base + k * TPB]);
        base += STEP;

        for (int c = 1; c < nfull; ++c) {
            float4 nxt[CHUNK];
            #pragma unroll
            for (int k = 0; k < CHUNK; ++k) nxt[k] = __ldcs(&xr4[base + k * TPB]);
            base += STEP;
            #pragma unroll
            for (int k = 0; k < CHUNK; ++k) {
                proc(buf[k].x); proc(buf[k].y); proc(buf[k].z); proc(buf[k].w);
            }
            #pragma unroll
            for (int k = 0; k < CHUNK; ++k) buf[k] = nxt[k];
        }
        #pragma unroll
        for (int k = 0; k < CHUNK; ++k) {
            proc(buf[k].x); proc(buf[k].y); proc(buf[k].z); proc(buf[k].w);
        }
    }

    // leftover float4s (prefetched in a small batch for MLP too)
    {
        int i = nfull * STEP + tid;
        for (; i + 3 * TPB < n4; i += 4 * TPB) {
            float4 v0 = __ldcs(&xr4[i]);
            float4 v1 = __ldcs(&xr4[i + TPB]);
            float4 v2 = __ldcs(&xr4[i + 2 * TPB]);
            float4 v3 = __ldcs(&xr4[i + 3 * TPB]);
            proc(v0.x); proc(v0.y); proc(v0.z); proc(v0.w);
            proc(v1.x); proc(v1.y); proc(v1.z); proc(v1.w);
            proc(v2.x); proc(v2.y); proc(v2.z); proc(v2.w);
            proc(v3.x); proc(v3.y); proc(v3.z); proc(v3.w);
        }
        for (; i < n4; i += TPB) {
            float4 v = __ldcs(&xr4[i]);
            proc(v.x); proc(v.y); proc(v.z); proc(v.w);
        }
    }
    // scalar tail
    for (int i = (n4 << 2) + tid; i < N; i += TPB) proc(xrow[i]);
    __syncthreads();

    // ---- reduce per-thread copies to per-bin totals (bank-swizzled) ----
    if (tid < MBINS) {
        const int b = tid;
        float s = 0.0f;
        #pragma unroll 16
        for (int t = 0; t < TPB; ++t)
            s += hist[b * TPB + ((t + b) & (TPB - 1))];
        bsum[b] = s;
    }
    __syncthreads();

    // ---- suffix sum: roc[j] = sum_{k>=j} full[k], full = [bsum[1..99], 0] ----
    if (tid == 0) {
        float acc = 0.0f;
        ssum[MBINS - 1] = 0.0f;               // tail provably 0 (x < 1 <= t[99])
        for (int k = MBINS - 2; k >= 0; --k) {
            acc += bsum[k + 1];
            ssum[k] = acc;
        }
    }
    __syncthreads();

    // ---- outputs ----
    const float yv = y[row];
    if (tid < MBINS) {
        const int j = tid;
        const float r = __fdiv_rn(ssum[j], yv);
        const float d0 = (j < MBINS - 1)
                         ? bsum[j + 1]
                         : (bsum[MBINS - 1] + bsum[MBINS - 2]) * 0.5f;
        const float d = __fdiv_rn(d0, yv);

        out[(size_t)row * MBINS + j] = r;
        out[(size_t)B * MBINS + (size_t)row * MBINS + j] = d;

        const float w = (j == 0 || j == MBINS - 1) ? 0.5f : 1.0f;
        atomicAdd(&tz[0], w * r);
        atomicAdd(&tz[1], w * d);
    }
    __syncthreads();
    if (tid == 0) {
        const size_t base2 = (size_t)2 * (size_t)B * MBINS;
        out[base2 + row]             = tz[0];
        out[base2 + (size_t)B + row] = tz[1];
    }
}

extern "C" void kernel_launch(void* const* d_in, const int* in_sizes, int n_in,
                              void* d_out, int out_size)
{
    const float* x = (const float*)d_in[0];
    const float* y = (const float*)d_in[1];
    const int B = in_sizes[1];
    const int N = in_sizes[0] / B;

    const size_t smem_bytes = (size_t)(MBINS * TPB + MBINS * 32 + 2 * MBINS + 2) * sizeof(float);
    cudaFuncSetAttribute(roc_kernel, cudaFuncAttributeMaxDynamicSharedMemorySize,
                         (int)smem_bytes);
    roc_kernel<<<B, TPB, smem_bytes>>>(x, y, (float*)d_out, B, N);
}